// round 7
// baseline (speedup 1.0000x reference)
#include <cuda_runtime.h>
#include <cuda_bf16.h>
#include <cstdint>

// Problem constants
#define HIDDEN 2048
#define INTER  1408
#define NEXP   60
#define TOPK   6

// Scratch (no cudaMalloc allowed)
__device__ __align__(16) float g_inter[TOPK * INTER]; // weighted silu(gate)*up

// Resolve topk_idx dtype inline: int64 per reference; accept int32 fallback.
__device__ __forceinline__ void resolve_experts(const void* idx_raw, int* s_exp) {
    if (threadIdx.x == 0) {
        const long long* p64 = (const long long*)idx_raw;
        const int*       p32 = (const int*)idx_raw;
        bool ok64 = true;
#pragma unroll
        for (int k = 0; k < TOPK; k++) {
            long long v = p64[k];
            if (v < 0 || v >= NEXP) ok64 = false;
        }
#pragma unroll
        for (int k = 0; k < TOPK; k++)
            s_exp[k] = ok64 ? (int)p64[k] : p32[k];
    }
}

// ---------------------------------------------------------------------------
// Kernel 1: for each (k, i):
//   g = dot(gate_row, x), u = dot(up_row, x)
//   g_inter[k*INTER+i] = silu(g) * u * topk_weights[k]
// One warp per (k,i), two independent DRAM streams/warp. x staged in smem.
// Block 0 zeroes `out` for the down kernel's atomics.
// ---------------------------------------------------------------------------
__global__ __launch_bounds__(256) void gateup_kernel(
    const float* __restrict__ x,
    const void*  __restrict__ idx_raw,
    const float* __restrict__ topk_w,
    const float* __restrict__ gate_up_all,
    float* __restrict__ out)
{
    __shared__ __align__(16) float s_x[HIDDEN];   // 8 KB
    __shared__ int s_exp[TOPK];

    resolve_experts(idx_raw, s_exp);

    // Stage x (512 float4, 2 per thread)
    {
        const float4* src = (const float4*)x;
        float4*       dst = (float4*)s_x;
#pragma unroll
        for (int t = 0; t < HIDDEN / 4 / 256; t++)
            dst[t * 256 + threadIdx.x] = src[t * 256 + threadIdx.x];
    }

    // Block 0 zeroes the output (down_kernel accumulates with atomics)
    if (blockIdx.x == 0) {
#pragma unroll
        for (int t = 0; t < HIDDEN / 256; t++)
            out[t * 256 + threadIdx.x] = 0.f;
    }
    __syncthreads();

    int gwarp = (blockIdx.x * blockDim.x + threadIdx.x) >> 5;
    int lane  = threadIdx.x & 31;
    if (gwarp >= TOPK * INTER) return;

    int k = gwarp / INTER;
    int i = gwarp - k * INTER;
    int e = s_exp[k];

    const float4* xv4  = (const float4*)s_x;
    const float4* grow = (const float4*)(gate_up_all + ((size_t)e * (2 * INTER) + i) * HIDDEN);
    const float4* urow = (const float4*)(gate_up_all + ((size_t)e * (2 * INTER) + INTER + i) * HIDDEN);

    float dg = 0.f, du = 0.f;
#pragma unroll
    for (int t = 0; t < HIDDEN / 4 / 32; t++) {   // 16 iterations
        int idx = t * 32 + lane;
        float4 xv = xv4[idx];                     // smem
        float4 gv = __ldcs(grow + idx);           // stream-once
        float4 uv = __ldcs(urow + idx);
        dg += xv.x * gv.x + xv.y * gv.y + xv.z * gv.z + xv.w * gv.w;
        du += xv.x * uv.x + xv.y * uv.y + xv.z * uv.z + xv.w * uv.w;
    }
#pragma unroll
    for (int o = 16; o; o >>= 1) {
        dg += __shfl_xor_sync(0xffffffffu, dg, o);
        du += __shfl_xor_sync(0xffffffffu, du, o);
    }
    if (lane == 0) {
        float s = dg / (1.f + __expf(-dg));        // silu
        g_inter[gwarp] = s * du * topk_w[k];
    }
}

// ---------------------------------------------------------------------------
// Kernel 2: warp per (k, h-pair): two adjacent output rows h0, h0+1 of expert
// k. The two weight rows are contiguous in DRAM (h-major) -> one warp streams
// 11.3 KB via TWO independent load streams (2x MLP, same shape that gets
// gateup to 6 TB/s). Shared b-load serves both accumulators. Partials combined
// with atomicAdd (REDG, per-address contention = TOPK = 6, negligible).
// ---------------------------------------------------------------------------
__global__ __launch_bounds__(256) void down_kernel(
    const void*  __restrict__ idx_raw,
    const float* __restrict__ down_all,
    float* __restrict__ out)
{
    __shared__ int s_exp[TOPK];
    resolve_experts(idx_raw, s_exp);
    __syncthreads();

    int warp  = threadIdx.x >> 5;
    int lane  = threadIdx.x & 31;
    int gwarp = blockIdx.x * 8 + warp;        // 0 .. 6143
    if (gwarp >= TOPK * HIDDEN / 2) return;

    int k  = gwarp >> 10;                     // / (HIDDEN/2)
    int h0 = (gwarp & (HIDDEN / 2 - 1)) << 1; // even row
    int e  = s_exp[k];

    const float4* row0 = (const float4*)(down_all + ((size_t)e * HIDDEN + h0) * INTER);
    const float4* row1 = row0 + INTER / 4;    // contiguous next row
    const float4* iv   = (const float4*)(g_inter + k * INTER);

    float acc0 = 0.f, acc1 = 0.f;
#pragma unroll
    for (int t = 0; t < INTER / 4 / 32; t++) {    // 11 iterations
        int idx = t * 32 + lane;
        float4 a0 = __ldcs(row0 + idx);           // stream 0
        float4 a1 = __ldcs(row1 + idx);           // stream 1
        float4 b  = __ldg (iv   + idx);           // L1/L2-hot
        acc0 += a0.x * b.x + a0.y * b.y + a0.z * b.z + a0.w * b.w;
        acc1 += a1.x * b.x + a1.y * b.y + a1.z * b.z + a1.w * b.w;
    }
#pragma unroll
    for (int o = 16; o; o >>= 1) {
        acc0 += __shfl_xor_sync(0xffffffffu, acc0, o);
        acc1 += __shfl_xor_sync(0xffffffffu, acc1, o);
    }
    if (lane == 0) {
        atomicAdd(out + h0,     acc0);
        atomicAdd(out + h0 + 1, acc1);
    }
}

// ---------------------------------------------------------------------------
// Inputs (metadata order):
//   0: x_bc1t        float32 [2048]
//   1: topk_idx      int64   [6]
//   2: topk_weights  float32 [6]
//   3: gate_up_all   float32 [60, 2816, 2048]
//   4: down_all      float32 [60, 2048, 1408]
// Output: float32 [2048]
// ---------------------------------------------------------------------------
extern "C" void kernel_launch(void* const* d_in, const int* in_sizes, int n_in,
                              void* d_out, int out_size) {
    const float* x    = (const float*)d_in[0];
    const void*  idx  = d_in[1];
    const float* w    = (const float*)d_in[2];
    const float* gu   = (const float*)d_in[3];
    const float* down = (const float*)d_in[4];
    float*       out  = (float*)d_out;

    int warps1 = TOPK * INTER;                 // 8448
    int blocks1 = (warps1 * 32 + 255) / 256;   // 1056
    gateup_kernel<<<blocks1, 256>>>(x, idx, w, gu, out);

    int blocks2 = (TOPK * HIDDEN / 2 * 32 + 255) / 256;  // 768
    down_kernel<<<blocks2, 256>>>(idx, down, out);
}

// round 8
// speedup vs baseline: 1.0062x; 1.0062x over previous
#include <cuda_runtime.h>
#include <cuda_bf16.h>
#include <cstdint>

// Problem constants
#define HIDDEN 2048
#define INTER  1408
#define NEXP   60
#define TOPK   6

// Scratch (no cudaMalloc allowed)
__device__ __align__(16) float g_inter[TOPK * INTER]; // weighted silu(gate)*up

// Resolve topk_idx dtype inline: int64 per reference; accept int32 fallback.
__device__ __forceinline__ void resolve_experts(const void* idx_raw, int* s_exp) {
    if (threadIdx.x == 0) {
        const long long* p64 = (const long long*)idx_raw;
        const int*       p32 = (const int*)idx_raw;
        bool ok64 = true;
#pragma unroll
        for (int k = 0; k < TOPK; k++) {
            long long v = p64[k];
            if (v < 0 || v >= NEXP) ok64 = false;
        }
#pragma unroll
        for (int k = 0; k < TOPK; k++)
            s_exp[k] = ok64 ? (int)p64[k] : p32[k];
    }
}

// ---------------------------------------------------------------------------
// Kernel 1: for each (k, i):
//   g = dot(gate_row, x), u = dot(up_row, x)
//   g_inter[k*INTER+i] = silu(g) * u * topk_weights[k]
// One warp per (k,i), two independent DRAM streams/warp. x staged in smem.
// Block 0 zeroes `out` for the down kernel's atomics.
// ---------------------------------------------------------------------------
__global__ __launch_bounds__(256) void gateup_kernel(
    const float* __restrict__ x,
    const void*  __restrict__ idx_raw,
    const float* __restrict__ topk_w,
    const float* __restrict__ gate_up_all,
    float* __restrict__ out)
{
    __shared__ __align__(16) float s_x[HIDDEN];   // 8 KB
    __shared__ int s_exp[TOPK];

    resolve_experts(idx_raw, s_exp);

    // Stage x (512 float4, 2 per thread)
    {
        const float4* src = (const float4*)x;
        float4*       dst = (float4*)s_x;
#pragma unroll
        for (int t = 0; t < HIDDEN / 4 / 256; t++)
            dst[t * 256 + threadIdx.x] = src[t * 256 + threadIdx.x];
    }

    // Block 0 zeroes the output (down_kernel accumulates with atomics)
    if (blockIdx.x == 0) {
#pragma unroll
        for (int t = 0; t < HIDDEN / 256; t++)
            out[t * 256 + threadIdx.x] = 0.f;
    }
    __syncthreads();

    int gwarp = (blockIdx.x * blockDim.x + threadIdx.x) >> 5;
    int lane  = threadIdx.x & 31;
    if (gwarp >= TOPK * INTER) return;

    int k = gwarp / INTER;
    int i = gwarp - k * INTER;
    int e = s_exp[k];

    const float4* xv4  = (const float4*)s_x;
    const float4* grow = (const float4*)(gate_up_all + ((size_t)e * (2 * INTER) + i) * HIDDEN);
    const float4* urow = (const float4*)(gate_up_all + ((size_t)e * (2 * INTER) + INTER + i) * HIDDEN);

    float dg = 0.f, du = 0.f;
#pragma unroll
    for (int t = 0; t < HIDDEN / 4 / 32; t++) {   // 16 iterations
        int idx = t * 32 + lane;
        float4 xv = xv4[idx];                     // smem
        float4 gv = __ldcs(grow + idx);           // stream-once
        float4 uv = __ldcs(urow + idx);
        dg += xv.x * gv.x + xv.y * gv.y + xv.z * gv.z + xv.w * gv.w;
        du += xv.x * uv.x + xv.y * uv.y + xv.z * uv.z + xv.w * uv.w;
    }
#pragma unroll
    for (int o = 16; o; o >>= 1) {
        dg += __shfl_xor_sync(0xffffffffu, dg, o);
        du += __shfl_xor_sync(0xffffffffu, du, o);
    }
    if (lane == 0) {
        float s = dg / (1.f + __expf(-dg));        // silu
        g_inter[gwarp] = s * du * topk_w[k];
    }
}

// ---------------------------------------------------------------------------
// Kernel 2: warp per (k, h-quad): FOUR adjacent output rows h0..h0+3 of
// expert k. The four weight rows are contiguous in DRAM (h-major) -> one warp
// streams 22.5 KB via FOUR independent load streams (4x MLP vs R5). Shared
// b-load amortized over 4 FMA chains. Partials via atomicAdd (REDG).
// 3072 warps, 384 blocks.
// ---------------------------------------------------------------------------
__global__ __launch_bounds__(256) void down_kernel(
    const void*  __restrict__ idx_raw,
    const float* __restrict__ down_all,
    float* __restrict__ out)
{
    __shared__ int s_exp[TOPK];
    resolve_experts(idx_raw, s_exp);
    __syncthreads();

    int warp  = threadIdx.x >> 5;
    int lane  = threadIdx.x & 31;
    int gwarp = blockIdx.x * 8 + warp;        // 0 .. 3071
    if (gwarp >= TOPK * HIDDEN / 4) return;

    int k  = gwarp / (HIDDEN / 4);            // expert slot
    int h0 = (gwarp - k * (HIDDEN / 4)) << 2; // first of 4 rows
    int e  = s_exp[k];

    const float4* row0 = (const float4*)(down_all + ((size_t)e * HIDDEN + h0) * INTER);
    const float4* row1 = row0 + 1 * (INTER / 4);
    const float4* row2 = row0 + 2 * (INTER / 4);
    const float4* row3 = row0 + 3 * (INTER / 4);
    const float4* iv   = (const float4*)(g_inter + k * INTER);

    float acc0 = 0.f, acc1 = 0.f, acc2 = 0.f, acc3 = 0.f;
#pragma unroll
    for (int t = 0; t < INTER / 4 / 32; t++) {    // 11 iterations
        int idx = t * 32 + lane;
        float4 a0 = __ldcs(row0 + idx);
        float4 a1 = __ldcs(row1 + idx);
        float4 a2 = __ldcs(row2 + idx);
        float4 a3 = __ldcs(row3 + idx);
        float4 b  = __ldg (iv   + idx);           // L1/L2-hot
        acc0 += a0.x * b.x + a0.y * b.y + a0.z * b.z + a0.w * b.w;
        acc1 += a1.x * b.x + a1.y * b.y + a1.z * b.z + a1.w * b.w;
        acc2 += a2.x * b.x + a2.y * b.y + a2.z * b.z + a2.w * b.w;
        acc3 += a3.x * b.x + a3.y * b.y + a3.z * b.z + a3.w * b.w;
    }
#pragma unroll
    for (int o = 16; o; o >>= 1) {
        acc0 += __shfl_xor_sync(0xffffffffu, acc0, o);
        acc1 += __shfl_xor_sync(0xffffffffu, acc1, o);
        acc2 += __shfl_xor_sync(0xffffffffu, acc2, o);
        acc3 += __shfl_xor_sync(0xffffffffu, acc3, o);
    }
    if (lane == 0) {
        atomicAdd(out + h0,     acc0);
        atomicAdd(out + h0 + 1, acc1);
        atomicAdd(out + h0 + 2, acc2);
        atomicAdd(out + h0 + 3, acc3);
    }
}

// ---------------------------------------------------------------------------
// Inputs (metadata order):
//   0: x_bc1t        float32 [2048]
//   1: topk_idx      int64   [6]
//   2: topk_weights  float32 [6]
//   3: gate_up_all   float32 [60, 2816, 2048]
//   4: down_all      float32 [60, 2048, 1408]
// Output: float32 [2048]
// ---------------------------------------------------------------------------
extern "C" void kernel_launch(void* const* d_in, const int* in_sizes, int n_in,
                              void* d_out, int out_size) {
    const float* x    = (const float*)d_in[0];
    const void*  idx  = d_in[1];
    const float* w    = (const float*)d_in[2];
    const float* gu   = (const float*)d_in[3];
    const float* down = (const float*)d_in[4];
    float*       out  = (float*)d_out;

    int warps1 = TOPK * INTER;                 // 8448
    int blocks1 = (warps1 * 32 + 255) / 256;   // 1056
    gateup_kernel<<<blocks1, 256>>>(x, idx, w, gu, out);

    int blocks2 = (TOPK * HIDDEN / 4 * 32 + 255) / 256;  // 384
    down_kernel<<<blocks2, 256>>>(idx, down, out);
}